// round 16
// baseline (speedup 1.0000x reference)
#include <cuda_runtime.h>
#include <math.h>
#include <stdint.h>

// ---------------- scratch (device globals; no allocation allowed) ----------------
__device__ float g_s  [256*256*64];
__device__ float g_c2 [128*128*256];
__device__ float g_c3 [64*64*512];
__device__ float g_c4 [32*32*1024];
__device__ float g_c5 [16*16*2048];
__device__ float g_p5 [16*16*256];
__device__ float g_p4 [32*32*256];
__device__ float g_p3 [64*64*256];
__device__ float g_p3o[64*64*256];
__device__ float g_t  [64*64*256];
__device__ float g_sc [64*64];
__device__ float g_c3p[3*4096*512];    // split-K partials for c3 (z=3)
__device__ float g_c4p[3*1024*1024];   // split-K partials for c4 (z=3)
__device__ float g_c5p[6*256*2048];    // split-K partials for c5 (z=6)
__device__ float g_p5p[8*256*256];     // split-K partials for l5
__device__ float g_op [3*4096*256];    // split-K partials for o3 / rpn (z=3)

// ---------------- packed f32x2 helpers ----------------
__device__ __forceinline__ void fma2(unsigned long long& c,
                                     unsigned long long a, unsigned long long b) {
    asm("fma.rn.f32x2 %0, %1, %2, %0;" : "+l"(c) : "l"(a), "l"(b));
}
__device__ __forceinline__ unsigned long long dup2(float x) {
    unsigned long long r;
    asm("mov.b64 %0, {%1, %1};" : "=l"(r) : "f"(x));
    return r;
}
__device__ __forceinline__ float2 unpk2(unsigned long long v) {
    float lo, hi;
    asm("mov.b64 {%0, %1}, %2;" : "=f"(lo), "=f"(hi) : "l"(v));
    return make_float2(lo, hi);
}

// ---------------- implicit-GEMM conv, dynamic smem, FFMA2 core ----------------
// MINBLK = min blocks/SM for launch_bounds (2 for 128x128/BK32, 3 for 64x128/BK16).
template<int KS, int STRIDE, int HIN, int WIN, int CIN, int COUT,
         bool RELU, bool ADDUP2, int BM, int BN, int BK, int SPLITK, int MINBLK>
__global__ __launch_bounds__(256, MINBLK) void conv_gemm_k(
    const float* __restrict__ in, const float* __restrict__ wgt,
    const float* __restrict__ up, float* __restrict__ out)
{
    constexpr int HOUT = (HIN + STRIDE - 1) / STRIDE;
    constexpr int WOUT = (WIN + STRIDE - 1) / STRIDE;
    constexpr int PTOTC = (HOUT - 1) * STRIDE + KS - HIN;
    constexpr int PAD  = (PTOTC > 0 ? PTOTC : 0) / 2;
    constexpr int K    = KS * KS * CIN;
    constexpr int KSEG = K / SPLITK;
    constexpr int NCH  = KSEG / BK;
    constexpr int TM   = BM / 16;
    constexpr int TN   = BN / 16;
    constexpr int TN2  = TN / 2;
    constexpr int RG   = TM / 4;
    constexpr int CG   = TN / 4;
    constexpr int NSUB = BK / 16;
    constexpr int AQ   = BM / 64;
    constexpr int BQ   = BN / 64;
    constexpr int MTOT = HOUT * WOUT;
    constexpr int ASTR = BM + 4;
    constexpr int ASZ  = BK * ASTR;
    constexpr int BSZ  = BK * BN;

    extern __shared__ float dsm[];
    float* As = dsm;
    float* Bs = dsm + 2 * ASZ;

    const int tid = threadIdx.x;
    const int bm = blockIdx.x * BM;
    const int bn = blockIdx.y * BN;
    const int kbase = blockIdx.z * KSEG;

    int a_m[AQ], a_k4[AQ], aoy[AQ], aox[AQ];
    #pragma unroll
    for (int aq = 0; aq < AQ; aq++) {
        const int q = tid + aq * 256;
        a_m[aq]  = (q >> 2) % BM;
        a_k4[aq] = ((q & 3) << 2) + ((q >> 2) / BM) * 0;  // only AQ*256 == BM*4 threads-quads
        const int am = bm + a_m[aq];
        aoy[aq] = am / WOUT;
        aox[aq] = am % WOUT;
    }
    // NOTE: for BM=64, AQ=1 and only k4 in {0,4,8,12} covered by (tid&3): 256 threads
    // cover 64 rows x 4 k-quads = exactly one 16-wide sub-chunk. For BM=128, AQ=2.
    int b_k[BQ], b_n4[BQ];
    #pragma unroll
    for (int bq = 0; bq < BQ; bq++) {
        const int q = tid + bq * 256;
        b_k[bq]  = q / (BN / 4);
        b_n4[bq] = (q % (BN / 4)) << 2;
    }

    const int tr0 = (tid >> 4) << 2;     // 0..60 (row within BM; BM=64 uses all)
    const int tc0 = (tid & 15) << 2;

    float4 ra[NSUB][AQ], rb[NSUB][BQ];

    auto load_chunk = [&](int k0) {
        const int kq  = k0 / CIN;
        const int cib = k0 % CIN;
        const int ky  = kq / KS;
        const int kx  = kq % KS;
        #pragma unroll
        for (int s = 0; s < NSUB; s++) {
            #pragma unroll
            for (int aq = 0; aq < AQ; aq++) {
                const int iy = aoy[aq] * STRIDE + ky - PAD;
                const int ix = aox[aq] * STRIDE + kx - PAD;
                float4 v = make_float4(0.f, 0.f, 0.f, 0.f);
                if (KS == 1 || (iy >= 0 && iy < HIN && ix >= 0 && ix < WIN))
                    v = *reinterpret_cast<const float4*>(
                        in + ((size_t)(iy * WIN + ix) * CIN + cib + s * 16 + a_k4[aq]));
                ra[s][aq] = v;
            }
            #pragma unroll
            for (int bq = 0; bq < BQ; bq++)
                rb[s][bq] = *reinterpret_cast<const float4*>(
                    wgt + (size_t)(k0 + s * 16 + b_k[bq]) * COUT + bn + b_n4[bq]);
        }
    };
    auto store_chunk = [&](int w) {
        float* Aw = As + w * ASZ;
        float* Bw = Bs + w * BSZ;
        #pragma unroll
        for (int s = 0; s < NSUB; s++) {
            #pragma unroll
            for (int aq = 0; aq < AQ; aq++) {
                const int kr = s * 16 + a_k4[aq];
                Aw[(kr + 0) * ASTR + a_m[aq]] = ra[s][aq].x;
                Aw[(kr + 1) * ASTR + a_m[aq]] = ra[s][aq].y;
                Aw[(kr + 2) * ASTR + a_m[aq]] = ra[s][aq].z;
                Aw[(kr + 3) * ASTR + a_m[aq]] = ra[s][aq].w;
            }
            #pragma unroll
            for (int bq = 0; bq < BQ; bq++)
                *reinterpret_cast<float4*>(
                    &Bw[(s * 16 + b_k[bq]) * BN + b_n4[bq]]) = rb[s][bq];
        }
    };

    unsigned long long acc2[TM][TN2];
    #pragma unroll
    for (int i = 0; i < TM; i++)
        #pragma unroll
        for (int j = 0; j < TN2; j++)
            acc2[i][j] = 0ull;

    load_chunk(kbase);
    store_chunk(0);
    __syncthreads();

    int db = 0;
    for (int c = 0; c < NCH; c++) {
        if (c + 1 < NCH) load_chunk(kbase + (c + 1) * BK);

        const float* Aw = As + db * ASZ;
        const float* Bw = Bs + db * BSZ;
        #pragma unroll
        for (int kk = 0; kk < BK; kk++) {
            float a[TM];
            #pragma unroll
            for (int g = 0; g < RG; g++) {
                const float4 v = *reinterpret_cast<const float4*>(
                    &Aw[kk * ASTR + tr0 + g * (BM / 2)]);
                a[g*4+0] = v.x; a[g*4+1] = v.y; a[g*4+2] = v.z; a[g*4+3] = v.w;
            }
            unsigned long long b2[TN2];
            #pragma unroll
            for (int h = 0; h < CG; h++) {
                const ulonglong2 u = *reinterpret_cast<const ulonglong2*>(
                    &Bw[kk * BN + tc0 + h * (BN / 2)]);
                b2[h*2+0] = u.x; b2[h*2+1] = u.y;
            }
            #pragma unroll
            for (int i = 0; i < TM; i++) {
                const unsigned long long ad = dup2(a[i]);
                #pragma unroll
                for (int j = 0; j < TN2; j++)
                    fma2(acc2[i][j], ad, b2[j]);
            }
        }

        if (c + 1 < NCH) store_chunk(db ^ 1);
        __syncthreads();
        db ^= 1;
    }

    #pragma unroll
    for (int i = 0; i < TM; i++) {
        const int m  = bm + tr0 + (TM == 4 ? i : ((i >> 2) * (BM / 2) + (i & 3)));
        const int oy = m / WOUT;
        const int ox = m % WOUT;
        #pragma unroll
        for (int h = 0; h < CG; h++) {
            const int ncol = bn + tc0 + h * (BN / 2);
            const float2 lo = unpk2(acc2[i][h*2+0]);
            const float2 hi = unpk2(acc2[i][h*2+1]);
            float4 r = make_float4(lo.x, lo.y, hi.x, hi.y);
            if (SPLITK > 1) {
                float* o = out + (size_t)blockIdx.z * MTOT * COUT;
                *reinterpret_cast<float4*>(o + (size_t)m * COUT + ncol) = r;
            } else {
                if (ADDUP2) {
                    const float4 u = *reinterpret_cast<const float4*>(
                        up + ((size_t)((oy >> 1) * (WOUT >> 1) + (ox >> 1)) * COUT + ncol));
                    r.x += u.x; r.y += u.y; r.z += u.z; r.w += u.w;
                }
                if (RELU) {
                    r.x = fmaxf(r.x, 0.f); r.y = fmaxf(r.y, 0.f);
                    r.z = fmaxf(r.z, 0.f); r.w = fmaxf(r.w, 0.f);
                }
                *reinterpret_cast<float4*>(out + (size_t)m * COUT + ncol) = r;
            }
        }
    }
}

// ---------------- split-K combine (+optional relu) ----------------
template<bool RELU, int SPLIT>
__global__ __launch_bounds__(256) void combine_k(
    const float* __restrict__ part, float* __restrict__ out, int n4)
{
    const int i = blockIdx.x * blockDim.x + threadIdx.x;
    if (i >= n4) return;
    float4 s = reinterpret_cast<const float4*>(part)[i];
    #pragma unroll
    for (int z = 1; z < SPLIT; z++) {
        const float4 v = reinterpret_cast<const float4*>(part)[i + (size_t)z * n4];
        s.x += v.x; s.y += v.y; s.z += v.z; s.w += v.w;
    }
    if (RELU) {
        s.x = fmaxf(s.x, 0.f); s.y = fmaxf(s.y, 0.f);
        s.z = fmaxf(s.z, 0.f); s.w = fmaxf(s.w, 0.f);
    }
    reinterpret_cast<float4*>(out)[i] = s;
}

// ---------------- stem: 7x7 s2, Cin=3 -> 64, relu ----------------
__global__ __launch_bounds__(512) void stem_kernel(
    const float* __restrict__ in, const float* __restrict__ w, float* __restrict__ out)
{
    __shared__ float ws[7*7*3*64];
    for (int i = threadIdx.y * 64 + threadIdx.x; i < 7*7*3*64; i += 512)
        ws[i] = w[i];
    __syncthreads();

    const int co = threadIdx.x;
    #pragma unroll
    for (int pp = 0; pp < 2; pp++) {
        const int p  = blockIdx.x * 16 + threadIdx.y * 2 + pp;
        const int oy = p >> 8;
        const int ox = p & 255;
        float acc = 0.f;
        #pragma unroll
        for (int ky = 0; ky < 7; ky++) {
            const int iy = oy * 2 + ky - 2;
            if (iy < 0 || iy >= 512) continue;
            #pragma unroll
            for (int kx = 0; kx < 7; kx++) {
                const int ix = ox * 2 + kx - 2;
                if (ix < 0 || ix >= 512) continue;
                const float* ip = in + (size_t)(iy * 512 + ix) * 3;
                const float* wp = ws + ((ky * 7 + kx) * 3) * 64 + co;
                acc = fmaf(ip[0], wp[0],   acc);
                acc = fmaf(ip[1], wp[64],  acc);
                acc = fmaf(ip[2], wp[128], acc);
            }
        }
        out[(size_t)p * 64 + co] = fmaxf(acc, 0.f);
    }
}

// ---------------- obj head (1x1, COUT=1) + sigmoid ----------------
__global__ __launch_bounds__(256) void obj_kernel(
    const float* __restrict__ t, const float* __restrict__ wobj, float* __restrict__ scores)
{
    const int p = blockIdx.x * 8 + (threadIdx.x >> 5);
    const int lane = threadIdx.x & 31;
    const float* tp = t + (size_t)p * 256;
    float acc = 0.f;
    #pragma unroll
    for (int c = 0; c < 256; c += 32)
        acc = fmaf(tp[c + lane], wobj[c + lane], acc);
    #pragma unroll
    for (int off = 16; off > 0; off >>= 1)
        acc += __shfl_xor_sync(0xFFFFFFFFu, acc, off);
    if (lane == 0)
        scores[p] = 1.f / (1.f + expf(-acc));
}

// ---------------- greedy NMS, 100 iterations, 4096 candidates ----------------
__global__ __launch_bounds__(1024) void nms_kernel(
    const float* __restrict__ scores, float* __restrict__ out)
{
    const int tid = threadIdx.x;
    float sw[4], by1[4], bx1[4], by2[4], bx2[4], bar[4];
    #pragma unroll
    for (int t = 0; t < 4; t++) {
        const int j = tid + t * 1024;
        sw[t] = scores[j];
        const float cy = (float)(j & 63) * (1.0f / 63.0f);
        const float cx = (float)(j >> 6) * (1.0f / 63.0f);
        by1[t] = fmaxf(cy - 0.05f, 0.f);
        bx1[t] = fmaxf(cx - 0.05f, 0.f);
        by2[t] = fminf(cy + 0.05f, 1.f);
        bx2[t] = fminf(cx + 0.05f, 1.f);
        bar[t] = (by2[t] - by1[t]) * (bx2[t] - bx1[t]);
    }

    __shared__ float s_v[32];
    __shared__ int   s_i[32];
    __shared__ float s_bestv;
    __shared__ int   s_besti;

    const int lane = tid & 31;
    const int warp = tid >> 5;

    for (int it = 0; it < 100; it++) {
        float bv = sw[0];
        int   bi = tid;
        #pragma unroll
        for (int t = 1; t < 4; t++) {
            const int j = tid + t * 1024;
            if (sw[t] > bv) { bv = sw[t]; bi = j; }
        }
        #pragma unroll
        for (int off = 16; off > 0; off >>= 1) {
            const float ov = __shfl_down_sync(0xFFFFFFFFu, bv, off);
            const int   oi = __shfl_down_sync(0xFFFFFFFFu, bi, off);
            if (ov > bv || (ov == bv && oi < bi)) { bv = ov; bi = oi; }
        }
        if (lane == 0) { s_v[warp] = bv; s_i[warp] = bi; }
        __syncthreads();
        if (warp == 0) {
            bv = s_v[lane]; bi = s_i[lane];
            #pragma unroll
            for (int off = 16; off > 0; off >>= 1) {
                const float ov = __shfl_down_sync(0xFFFFFFFFu, bv, off);
                const int   oi = __shfl_down_sync(0xFFFFFFFFu, bi, off);
                if (ov > bv || (ov == bv && oi < bi)) { bv = ov; bi = oi; }
            }
            if (lane == 0) { s_bestv = bv; s_besti = bi; }
        }
        __syncthreads();

        const float bestv = s_bestv;
        const int   besti = s_besti;
        const float bcy = (float)(besti & 63) * (1.0f / 63.0f);
        const float bcx = (float)(besti >> 6) * (1.0f / 63.0f);
        const float y1b = fmaxf(bcy - 0.05f, 0.f);
        const float x1b = fmaxf(bcx - 0.05f, 0.f);
        const float y2b = fminf(bcy + 0.05f, 1.f);
        const float x2b = fminf(bcx + 0.05f, 1.f);
        const float areab = (y2b - y1b) * (x2b - x1b);
        const bool valid = bestv > -5e29f;

        if (tid == 0) {
            out[it * 4 + 0] = valid ? y1b : 0.f;
            out[it * 4 + 1] = valid ? x1b : 0.f;
            out[it * 4 + 2] = valid ? y2b : 0.f;
            out[it * 4 + 3] = valid ? x2b : 0.f;
            out[400 + it]   = valid ? bestv : 0.f;
        }

        #pragma unroll
        for (int t = 0; t < 4; t++) {
            const float yy1 = fmaxf(y1b, by1[t]);
            const float xx1 = fmaxf(x1b, bx1[t]);
            const float yy2 = fminf(y2b, by2[t]);
            const float xx2 = fminf(x2b, bx2[t]);
            const float inter = fmaxf(yy2 - yy1, 0.f) * fmaxf(xx2 - xx1, 0.f);
            const float iou = inter / (areab + bar[t] - inter + 1e-9f);
            if (iou > 0.5f) sw[t] = -1e30f;
        }
        __syncthreads();
    }
}

// ---------------- orchestration ----------------
extern "C" void kernel_launch(void* const* d_in, const int* in_sizes, int n_in,
                              void* d_out, int out_size)
{
    (void)in_sizes; (void)n_in; (void)out_size;
    const float* inp    = (const float*)d_in[0];
    const float* w_stem = (const float*)d_in[1];
    const float* w_c2   = (const float*)d_in[2];
    const float* w_c3   = (const float*)d_in[3];
    const float* w_c4   = (const float*)d_in[4];
    const float* w_c5   = (const float*)d_in[5];
    const float* l3     = (const float*)d_in[6];
    const float* l4     = (const float*)d_in[7];
    const float* l5     = (const float*)d_in[8];
    const float* o3     = (const float*)d_in[9];
    const float* w_rpn  = (const float*)d_in[12];
    const float* w_obj  = (const float*)d_in[13];
    float* out = (float*)d_out;

    void *ps, *pc2, *pc3, *pc4, *pc5, *pp5, *pp4, *pp3, *pp3o, *pt, *psc;
    void *pc3p, *pc4p, *pc5p, *pp5p, *pop;
    cudaGetSymbolAddress(&ps, g_s);     cudaGetSymbolAddress(&pc2, g_c2);
    cudaGetSymbolAddress(&pc3, g_c3);   cudaGetSymbolAddress(&pc4, g_c4);
    cudaGetSymbolAddress(&pc5, g_c5);   cudaGetSymbolAddress(&pp5, g_p5);
    cudaGetSymbolAddress(&pp4, g_p4);   cudaGetSymbolAddress(&pp3, g_p3);
    cudaGetSymbolAddress(&pp3o, g_p3o); cudaGetSymbolAddress(&pt, g_t);
    cudaGetSymbolAddress(&psc, g_sc);   cudaGetSymbolAddress(&pc3p, g_c3p);
    cudaGetSymbolAddress(&pc4p, g_c4p); cudaGetSymbolAddress(&pc5p, g_c5p);
    cudaGetSymbolAddress(&pp5p, g_p5p); cudaGetSymbolAddress(&pop, g_op);
    float *s_ = (float*)ps, *c2 = (float*)pc2, *c3 = (float*)pc3, *c4 = (float*)pc4;
    float *c5 = (float*)pc5, *p5 = (float*)pp5, *p4 = (float*)pp4, *p3 = (float*)pp3;
    float *p3o = (float*)pp3o, *tb = (float*)pt, *sc = (float*)psc;
    float *c3p = (float*)pc3p, *c4p = (float*)pc4p, *c5p = (float*)pc5p;
    float *p5p = (float*)pp5p, *op = (float*)pop;

    constexpr int SM_C2  = (2*32*(128+4) + 2*32*128) * 4;   // 66560 B (128x128, BK32)
    constexpr int SM_NEW = (2*16*( 64+4) + 2*16*128) * 4;   // 25088 B (64x128, BK16)
    constexpr int SM_1X1 = (2*16*( 64+4) + 2*16* 64) * 4;   // 16896 B (64x64, BK16)

    cudaFuncSetAttribute(conv_gemm_k<3,2,256,256,  64, 256,true ,false,128,128,32,1,2>, cudaFuncAttributeMaxDynamicSharedMemorySize, SM_C2);

    // backbone
    stem_kernel<<<4096, dim3(64, 8)>>>(inp, w_stem, s_);
    // c2: proven 128x128/BK32/2CTA shape
    conv_gemm_k<3,2,256,256,  64, 256,true ,false,128,128,32,1,2><<<dim3(128,2,1), 256, SM_C2>>>(s_, w_c2, nullptr, c2);
    // c3: 64x128/BK16/3CTA, z=3 -> 768 blocks
    conv_gemm_k<3,2,128,128, 256, 512,false,false, 64,128,16,3,3><<<dim3( 64,4,3), 256, SM_NEW>>>(c2, w_c3, nullptr, c3p);
    combine_k<true, 3><<<2048, 256>>>(c3p, c3, 4096 * 512 / 4);
    // c4: z=3 -> 384 blocks
    conv_gemm_k<3,2, 64, 64, 512,1024,false,false, 64,128,16,3,3><<<dim3( 16,8,3), 256, SM_NEW>>>(c3, w_c4, nullptr, c4p);
    combine_k<true, 3><<<1024, 256>>>(c4p, c4, 1024 * 1024 / 4);
    // c5: z=6 -> 384 blocks
    conv_gemm_k<3,2, 32, 32,1024,2048,false,false, 64,128,16,6,3><<<dim3(  4,16,6), 256, SM_NEW>>>(c4, w_c5, nullptr, c5p);
    combine_k<true, 6><<<512, 256>>>(c5p, c5, 256 * 2048 / 4);
    // FPN (only p3 path live)
    conv_gemm_k<1,1, 16, 16,2048, 256,false,false, 64, 64,16,8,2><<<dim3(  4,4,8), 256, SM_1X1>>>(c5, l5, nullptr, p5p);
    combine_k<false, 8><<<64, 256>>>(p5p, p5, 256 * 256 / 4);
    conv_gemm_k<1,1, 32, 32,1024, 256,false,true , 64, 64,16,1,2><<<dim3( 16,4,1), 256, SM_1X1>>>(c4, l4, p5, p4);
    conv_gemm_k<1,1, 64, 64, 512, 256,false,true , 64, 64,16,1,2><<<dim3( 64,4,1), 256, SM_1X1>>>(c3, l3, p4, p3);
    // RPN head path: z=3 -> 384 blocks each
    conv_gemm_k<3,1, 64, 64, 256, 256,false,false, 64,128,16,3,3><<<dim3( 64,2,3), 256, SM_NEW>>>(p3, o3, nullptr, op);
    combine_k<false, 3><<<1024, 256>>>(op, p3o, 4096 * 256 / 4);
    conv_gemm_k<3,1, 64, 64, 256, 256,false,false, 64,128,16,3,3><<<dim3( 64,2,3), 256, SM_NEW>>>(p3o, w_rpn, nullptr, op);
    combine_k<true, 3><<<1024, 256>>>(op, tb, 4096 * 256 / 4);
    obj_kernel<<<512, 256>>>(tb, w_obj, sc);
    nms_kernel<<<1, 1024>>>(sc, out);
}

// round 17
// speedup vs baseline: 1.1890x; 1.1890x over previous
#include <cuda_runtime.h>
#include <math.h>
#include <stdint.h>

// ---------------- scratch (device globals; no allocation allowed) ----------------
__device__ float g_s  [256*256*64];
__device__ float g_c2 [128*128*256];
__device__ float g_c3 [64*64*512];
__device__ float g_c4 [32*32*1024];
__device__ float g_c5 [16*16*2048];
__device__ float g_p5 [16*16*256];
__device__ float g_p4 [32*32*256];
__device__ float g_p3 [64*64*256];
__device__ float g_p3o[64*64*256];
__device__ float g_t  [64*64*256];
__device__ float g_sc [64*64];
__device__ float g_c3p[2*4096*512];    // split-K partials for c3
__device__ float g_c4p[9*1024*1024];   // split-K partials for c4 (z=9)
__device__ float g_c5p[18*256*2048];   // split-K partials for c5 (z=18)
__device__ float g_p5p[8*256*256];     // split-K partials for l5
__device__ float g_op [9*4096*256];    // split-K partials for o3 / rpn (z=9)

// ---------------- packed f32x2 helpers ----------------
__device__ __forceinline__ void fma2(unsigned long long& c,
                                     unsigned long long a, unsigned long long b) {
    asm("fma.rn.f32x2 %0, %1, %2, %0;" : "+l"(c) : "l"(a), "l"(b));
}
__device__ __forceinline__ unsigned long long dup2(float x) {
    unsigned long long r;
    asm("mov.b64 %0, {%1, %1};" : "=l"(r) : "f"(x));
    return r;
}
__device__ __forceinline__ float2 unpk2(unsigned long long v) {
    float lo, hi;
    asm("mov.b64 {%0, %1}, %2;" : "=f"(lo), "=f"(hi) : "l"(v));
    return make_float2(lo, hi);
}

// ---------------- implicit-GEMM conv, dynamic smem, FFMA2 + cp.async(B) ----------------
template<int KS, int STRIDE, int HIN, int WIN, int CIN, int COUT,
         bool RELU, bool ADDUP2, int BM, int BN, int BK, int SPLITK>
__global__ __launch_bounds__(256, 2) void conv_gemm_k(
    const float* __restrict__ in, const float* __restrict__ wgt,
    const float* __restrict__ up, float* __restrict__ out)
{
    constexpr int HOUT = (HIN + STRIDE - 1) / STRIDE;
    constexpr int WOUT = (WIN + STRIDE - 1) / STRIDE;
    constexpr int PTOTC = (HOUT - 1) * STRIDE + KS - HIN;
    constexpr int PAD  = (PTOTC > 0 ? PTOTC : 0) / 2;
    constexpr int K    = KS * KS * CIN;
    constexpr int KSEG = K / SPLITK;
    constexpr int NCH  = KSEG / BK;
    constexpr int TM   = BM / 16;
    constexpr int TN   = BN / 16;
    constexpr int TN2  = TN / 2;
    constexpr int RG   = TM / 4;
    constexpr int CG   = TN / 4;
    constexpr int NSUB = BK / 16;
    constexpr int AQ   = BM / 64;
    constexpr int BQ   = BN / 64;
    constexpr int MTOT = HOUT * WOUT;
    constexpr int ASTR = BM + 4;
    constexpr int ASZ  = BK * ASTR;
    constexpr int BSZ  = BK * BN;

    extern __shared__ float dsm[];
    float* As = dsm;
    float* Bs = dsm + 2 * ASZ;

    const int tid = threadIdx.x;
    const int bm = blockIdx.x * BM;
    const int bn = blockIdx.y * BN;
    const int kbase = blockIdx.z * KSEG;

    int a_m[AQ], a_k4[AQ], aoy[AQ], aox[AQ];
    #pragma unroll
    for (int aq = 0; aq < AQ; aq++) {
        const int q = tid + aq * 256;
        a_m[aq]  = q >> 2;
        a_k4[aq] = (q & 3) << 2;
        const int am = bm + a_m[aq];
        aoy[aq] = am / WOUT;
        aox[aq] = am % WOUT;
    }
    int b_k[BQ], b_n4[BQ];
    #pragma unroll
    for (int bq = 0; bq < BQ; bq++) {
        const int q = tid + bq * 256;
        b_k[bq]  = q / (BN / 4);
        b_n4[bq] = (q % (BN / 4)) << 2;
    }

    const int tr0 = (tid >> 4) << 2;
    const int tc0 = (tid & 15) << 2;

    float4 ra[NSUB][AQ];

    auto load_a = [&](int k0) {
        const int kq  = k0 / CIN;
        const int cib = k0 % CIN;
        const int ky  = kq / KS;
        const int kx  = kq % KS;
        #pragma unroll
        for (int s = 0; s < NSUB; s++) {
            #pragma unroll
            for (int aq = 0; aq < AQ; aq++) {
                const int iy = aoy[aq] * STRIDE + ky - PAD;
                const int ix = aox[aq] * STRIDE + kx - PAD;
                float4 v = make_float4(0.f, 0.f, 0.f, 0.f);
                if (KS == 1 || (iy >= 0 && iy < HIN && ix >= 0 && ix < WIN))
                    v = *reinterpret_cast<const float4*>(
                        in + ((size_t)(iy * WIN + ix) * CIN + cib + s * 16 + a_k4[aq]));
                ra[s][aq] = v;
            }
        }
    };
    auto store_a = [&](int w) {
        float* Aw = As + w * ASZ;
        #pragma unroll
        for (int s = 0; s < NSUB; s++) {
            #pragma unroll
            for (int aq = 0; aq < AQ; aq++) {
                const int kr = s * 16 + a_k4[aq];
                Aw[(kr + 0) * ASTR + a_m[aq]] = ra[s][aq].x;
                Aw[(kr + 1) * ASTR + a_m[aq]] = ra[s][aq].y;
                Aw[(kr + 2) * ASTR + a_m[aq]] = ra[s][aq].z;
                Aw[(kr + 3) * ASTR + a_m[aq]] = ra[s][aq].w;
            }
        }
    };
    auto cpasync_b = [&](int w, int k0) {
        float* Bw = Bs + w * BSZ;
        #pragma unroll
        for (int s = 0; s < NSUB; s++) {
            #pragma unroll
            for (int bq = 0; bq < BQ; bq++) {
                const float* src = wgt + (size_t)(k0 + s * 16 + b_k[bq]) * COUT + bn + b_n4[bq];
                const uint32_t dst = (uint32_t)__cvta_generic_to_shared(
                    &Bw[(s * 16 + b_k[bq]) * BN + b_n4[bq]]);
                asm volatile("cp.async.cg.shared.global [%0], [%1], 16;"
                             :: "r"(dst), "l"(src));
            }
        }
        asm volatile("cp.async.commit_group;");
    };

    unsigned long long acc2[TM][TN2];
    #pragma unroll
    for (int i = 0; i < TM; i++)
        #pragma unroll
        for (int j = 0; j < TN2; j++)
            acc2[i][j] = 0ull;

    cpasync_b(0, kbase);
    load_a(kbase);
    store_a(0);
    asm volatile("cp.async.wait_group 0;" ::: "memory");
    __syncthreads();

    int db = 0;
    for (int c = 0; c < NCH; c++) {
        if (c + 1 < NCH) {
            cpasync_b(db ^ 1, kbase + (c + 1) * BK);
            load_a(kbase + (c + 1) * BK);
        }

        const float* Aw = As + db * ASZ;
        const float* Bw = Bs + db * BSZ;
        #pragma unroll
        for (int kk = 0; kk < BK; kk++) {
            float a[TM];
            #pragma unroll
            for (int g = 0; g < RG; g++) {
                const float4 v = *reinterpret_cast<const float4*>(
                    &Aw[kk * ASTR + tr0 + g * (BM / 2)]);
                a[g*4+0] = v.x; a[g*4+1] = v.y; a[g*4+2] = v.z; a[g*4+3] = v.w;
            }
            unsigned long long b2[TN2];
            #pragma unroll
            for (int h = 0; h < CG; h++) {
                const ulonglong2 u = *reinterpret_cast<const ulonglong2*>(
                    &Bw[kk * BN + tc0 + h * (BN / 2)]);
                b2[h*2+0] = u.x; b2[h*2+1] = u.y;
            }
            #pragma unroll
            for (int i = 0; i < TM; i++) {
                const unsigned long long ad = dup2(a[i]);
                #pragma unroll
                for (int j = 0; j < TN2; j++)
                    fma2(acc2[i][j], ad, b2[j]);
            }
        }

        if (c + 1 < NCH) {
            store_a(db ^ 1);
            asm volatile("cp.async.wait_group 0;" ::: "memory");
        }
        __syncthreads();
        db ^= 1;
    }

    #pragma unroll
    for (int i = 0; i < TM; i++) {
        const int m  = bm + tr0 + (i >> 2) * (BM / 2) + (i & 3);
        const int oy = m / WOUT;
        const int ox = m % WOUT;
        #pragma unroll
        for (int h = 0; h < CG; h++) {
            const int ncol = bn + tc0 + h * (BN / 2);
            const float2 lo = unpk2(acc2[i][h*2+0]);
            const float2 hi = unpk2(acc2[i][h*2+1]);
            float4 r = make_float4(lo.x, lo.y, hi.x, hi.y);
            if (SPLITK > 1) {
                float* o = out + (size_t)blockIdx.z * MTOT * COUT;
                *reinterpret_cast<float4*>(o + (size_t)m * COUT + ncol) = r;
            } else {
                if (ADDUP2) {
                    const float4 u = *reinterpret_cast<const float4*>(
                        up + ((size_t)((oy >> 1) * (WOUT >> 1) + (ox >> 1)) * COUT + ncol));
                    r.x += u.x; r.y += u.y; r.z += u.z; r.w += u.w;
                }
                if (RELU) {
                    r.x = fmaxf(r.x, 0.f); r.y = fmaxf(r.y, 0.f);
                    r.z = fmaxf(r.z, 0.f); r.w = fmaxf(r.w, 0.f);
                }
                *reinterpret_cast<float4*>(out + (size_t)m * COUT + ncol) = r;
            }
        }
    }
}

// ---------------- split-K combine (+optional relu) ----------------
template<bool RELU, int SPLIT>
__global__ __launch_bounds__(256) void combine_k(
    const float* __restrict__ part, float* __restrict__ out, int n4)
{
    const int i = blockIdx.x * blockDim.x + threadIdx.x;
    if (i >= n4) return;
    float4 s = reinterpret_cast<const float4*>(part)[i];
    #pragma unroll
    for (int z = 1; z < SPLIT; z++) {
        const float4 v = reinterpret_cast<const float4*>(part)[i + (size_t)z * n4];
        s.x += v.x; s.y += v.y; s.z += v.z; s.w += v.w;
    }
    if (RELU) {
        s.x = fmaxf(s.x, 0.f); s.y = fmaxf(s.y, 0.f);
        s.z = fmaxf(s.z, 0.f); s.w = fmaxf(s.w, 0.f);
    }
    reinterpret_cast<float4*>(out)[i] = s;
}

// ---------------- stem: 7x7 s2, Cin=3 -> 64, relu ----------------
__global__ __launch_bounds__(512) void stem_kernel(
    const float* __restrict__ in, const float* __restrict__ w, float* __restrict__ out)
{
    __shared__ float ws[7*7*3*64];
    for (int i = threadIdx.y * 64 + threadIdx.x; i < 7*7*3*64; i += 512)
        ws[i] = w[i];
    __syncthreads();

    const int co = threadIdx.x;
    #pragma unroll
    for (int pp = 0; pp < 2; pp++) {
        const int p  = blockIdx.x * 16 + threadIdx.y * 2 + pp;
        const int oy = p >> 8;
        const int ox = p & 255;
        float acc = 0.f;
        #pragma unroll
        for (int ky = 0; ky < 7; ky++) {
            const int iy = oy * 2 + ky - 2;
            if (iy < 0 || iy >= 512) continue;
            #pragma unroll
            for (int kx = 0; kx < 7; kx++) {
                const int ix = ox * 2 + kx - 2;
                if (ix < 0 || ix >= 512) continue;
                const float* ip = in + (size_t)(iy * 512 + ix) * 3;
                const float* wp = ws + ((ky * 7 + kx) * 3) * 64 + co;
                acc = fmaf(ip[0], wp[0],   acc);
                acc = fmaf(ip[1], wp[64],  acc);
                acc = fmaf(ip[2], wp[128], acc);
            }
        }
        out[(size_t)p * 64 + co] = fmaxf(acc, 0.f);
    }
}

// ---------------- obj head (1x1, COUT=1) + sigmoid ----------------
__global__ __launch_bounds__(256) void obj_kernel(
    const float* __restrict__ t, const float* __restrict__ wobj, float* __restrict__ scores)
{
    const int p = blockIdx.x * 8 + (threadIdx.x >> 5);
    const int lane = threadIdx.x & 31;
    const float* tp = t + (size_t)p * 256;
    float acc = 0.f;
    #pragma unroll
    for (int c = 0; c < 256; c += 32)
        acc = fmaf(tp[c + lane], wobj[c + lane], acc);
    #pragma unroll
    for (int off = 16; off > 0; off >>= 1)
        acc += __shfl_xor_sync(0xFFFFFFFFu, acc, off);
    if (lane == 0)
        scores[p] = 1.f / (1.f + expf(-acc));
}

// ---------------- greedy NMS, 100 iterations, 4096 candidates ----------------
__global__ __launch_bounds__(1024) void nms_kernel(
    const float* __restrict__ scores, float* __restrict__ out)
{
    const int tid = threadIdx.x;
    float sw[4], by1[4], bx1[4], by2[4], bx2[4], bar[4];
    #pragma unroll
    for (int t = 0; t < 4; t++) {
        const int j = tid + t * 1024;
        sw[t] = scores[j];
        const float cy = (float)(j & 63) * (1.0f / 63.0f);
        const float cx = (float)(j >> 6) * (1.0f / 63.0f);
        by1[t] = fmaxf(cy - 0.05f, 0.f);
        bx1[t] = fmaxf(cx - 0.05f, 0.f);
        by2[t] = fminf(cy + 0.05f, 1.f);
        bx2[t] = fminf(cx + 0.05f, 1.f);
        bar[t] = (by2[t] - by1[t]) * (bx2[t] - bx1[t]);
    }

    __shared__ float s_v[32];
    __shared__ int   s_i[32];
    __shared__ float s_bestv;
    __shared__ int   s_besti;

    const int lane = tid & 31;
    const int warp = tid >> 5;

    for (int it = 0; it < 100; it++) {
        float bv = sw[0];
        int   bi = tid;
        #pragma unroll
        for (int t = 1; t < 4; t++) {
            const int j = tid + t * 1024;
            if (sw[t] > bv) { bv = sw[t]; bi = j; }
        }
        #pragma unroll
        for (int off = 16; off > 0; off >>= 1) {
            const float ov = __shfl_down_sync(0xFFFFFFFFu, bv, off);
            const int   oi = __shfl_down_sync(0xFFFFFFFFu, bi, off);
            if (ov > bv || (ov == bv && oi < bi)) { bv = ov; bi = oi; }
        }
        if (lane == 0) { s_v[warp] = bv; s_i[warp] = bi; }
        __syncthreads();
        if (warp == 0) {
            bv = s_v[lane]; bi = s_i[lane];
            #pragma unroll
            for (int off = 16; off > 0; off >>= 1) {
                const float ov = __shfl_down_sync(0xFFFFFFFFu, bv, off);
                const int   oi = __shfl_down_sync(0xFFFFFFFFu, bi, off);
                if (ov > bv || (ov == bv && oi < bi)) { bv = ov; bi = oi; }
            }
            if (lane == 0) { s_bestv = bv; s_besti = bi; }
        }
        __syncthreads();

        const float bestv = s_bestv;
        const int   besti = s_besti;
        const float bcy = (float)(besti & 63) * (1.0f / 63.0f);
        const float bcx = (float)(besti >> 6) * (1.0f / 63.0f);
        const float y1b = fmaxf(bcy - 0.05f, 0.f);
        const float x1b = fmaxf(bcx - 0.05f, 0.f);
        const float y2b = fminf(bcy + 0.05f, 1.f);
        const float x2b = fminf(bcx + 0.05f, 1.f);
        const float areab = (y2b - y1b) * (x2b - x1b);
        const bool valid = bestv > -5e29f;

        if (tid == 0) {
            out[it * 4 + 0] = valid ? y1b : 0.f;
            out[it * 4 + 1] = valid ? x1b : 0.f;
            out[it * 4 + 2] = valid ? y2b : 0.f;
            out[it * 4 + 3] = valid ? x2b : 0.f;
            out[400 + it]   = valid ? bestv : 0.f;
        }

        #pragma unroll
        for (int t = 0; t < 4; t++) {
            const float yy1 = fmaxf(y1b, by1[t]);
            const float xx1 = fmaxf(x1b, bx1[t]);
            const float yy2 = fminf(y2b, by2[t]);
            const float xx2 = fminf(x2b, bx2[t]);
            const float inter = fmaxf(yy2 - yy1, 0.f) * fmaxf(xx2 - xx1, 0.f);
            const float iou = inter / (areab + bar[t] - inter + 1e-9f);
            if (iou > 0.5f) sw[t] = -1e30f;
        }
        __syncthreads();
    }
}

// ---------------- orchestration ----------------
extern "C" void kernel_launch(void* const* d_in, const int* in_sizes, int n_in,
                              void* d_out, int out_size)
{
    (void)in_sizes; (void)n_in; (void)out_size;
    const float* inp    = (const float*)d_in[0];
    const float* w_stem = (const float*)d_in[1];
    const float* w_c2   = (const float*)d_in[2];
    const float* w_c3   = (const float*)d_in[3];
    const float* w_c4   = (const float*)d_in[4];
    const float* w_c5   = (const float*)d_in[5];
    const float* l3     = (const float*)d_in[6];
    const float* l4     = (const float*)d_in[7];
    const float* l5     = (const float*)d_in[8];
    const float* o3     = (const float*)d_in[9];
    const float* w_rpn  = (const float*)d_in[12];
    const float* w_obj  = (const float*)d_in[13];
    float* out = (float*)d_out;

    void *ps, *pc2, *pc3, *pc4, *pc5, *pp5, *pp4, *pp3, *pp3o, *pt, *psc;
    void *pc3p, *pc4p, *pc5p, *pp5p, *pop;
    cudaGetSymbolAddress(&ps, g_s);     cudaGetSymbolAddress(&pc2, g_c2);
    cudaGetSymbolAddress(&pc3, g_c3);   cudaGetSymbolAddress(&pc4, g_c4);
    cudaGetSymbolAddress(&pc5, g_c5);   cudaGetSymbolAddress(&pp5, g_p5);
    cudaGetSymbolAddress(&pp4, g_p4);   cudaGetSymbolAddress(&pp3, g_p3);
    cudaGetSymbolAddress(&pp3o, g_p3o); cudaGetSymbolAddress(&pt, g_t);
    cudaGetSymbolAddress(&psc, g_sc);   cudaGetSymbolAddress(&pc3p, g_c3p);
    cudaGetSymbolAddress(&pc4p, g_c4p); cudaGetSymbolAddress(&pc5p, g_c5p);
    cudaGetSymbolAddress(&pp5p, g_p5p); cudaGetSymbolAddress(&pop, g_op);
    float *s_ = (float*)ps, *c2 = (float*)pc2, *c3 = (float*)pc3, *c4 = (float*)pc4;
    float *c5 = (float*)pc5, *p5 = (float*)pp5, *p4 = (float*)pp4, *p3 = (float*)pp3;
    float *p3o = (float*)pp3o, *tb = (float*)pt, *sc = (float*)psc;
    float *c3p = (float*)pc3p, *c4p = (float*)pc4p, *c5p = (float*)pc5p;
    float *p5p = (float*)pp5p, *op = (float*)pop;

    constexpr int SM_BIG = (2*32*(128+4) + 2*32*128) * 4;   // 66560 B
    constexpr int SM_1X1 = (2*16*(64+4)  + 2*16*64)  * 4;   // 16896 B

    cudaFuncSetAttribute(conv_gemm_k<3,2,256,256,  64, 256,true ,false,128,128,32,1>,  cudaFuncAttributeMaxDynamicSharedMemorySize, SM_BIG);
    cudaFuncSetAttribute(conv_gemm_k<3,2,128,128, 256, 512,false,false,128,128,32,2>,  cudaFuncAttributeMaxDynamicSharedMemorySize, SM_BIG);
    cudaFuncSetAttribute(conv_gemm_k<3,2, 64, 64, 512,1024,false,false,128,128,32,9>,  cudaFuncAttributeMaxDynamicSharedMemorySize, SM_BIG);
    cudaFuncSetAttribute(conv_gemm_k<3,2, 32, 32,1024,2048,false,false,128,128,32,18>, cudaFuncAttributeMaxDynamicSharedMemorySize, SM_BIG);
    cudaFuncSetAttribute(conv_gemm_k<3,1, 64, 64, 256, 256,false,false,128,128,32,9>,  cudaFuncAttributeMaxDynamicSharedMemorySize, SM_BIG);

    // backbone — R15 grids (best), cp.async B-path
    stem_kernel<<<4096, dim3(64, 8)>>>(inp, w_stem, s_);
    conv_gemm_k<3,2,256,256,  64, 256,true ,false,128,128,32,1><<<dim3(128,2,1),  256, SM_BIG>>>(s_, w_c2, nullptr, c2);
    conv_gemm_k<3,2,128,128, 256, 512,false,false,128,128,32,2><<<dim3( 32,4,2),  256, SM_BIG>>>(c2, w_c3, nullptr, c3p);
    combine_k<true, 2><<<2048, 256>>>(c3p, c3, 4096 * 512 / 4);
    conv_gemm_k<3,2, 64, 64, 512,1024,false,false,128,128,32,9><<<dim3(  8,8,9),  256, SM_BIG>>>(c3, w_c4, nullptr, c4p);
    combine_k<true, 9><<<1024, 256>>>(c4p, c4, 1024 * 1024 / 4);
    conv_gemm_k<3,2, 32, 32,1024,2048,false,false,128,128,32,18><<<dim3( 2,16,18), 256, SM_BIG>>>(c4, w_c5, nullptr, c5p);
    combine_k<true, 18><<<512, 256>>>(c5p, c5, 256 * 2048 / 4);
    // FPN (only p3 path live)
    conv_gemm_k<1,1, 16, 16,2048, 256,false,false, 64, 64,16,8><<<dim3(  4,4,8), 256, SM_1X1>>>(c5, l5, nullptr, p5p);
    combine_k<false, 8><<<64, 256>>>(p5p, p5, 256 * 256 / 4);
    conv_gemm_k<1,1, 32, 32,1024, 256,false,true , 64, 64,16,1><<<dim3( 16,4,1), 256, SM_1X1>>>(c4, l4, p5, p4);
    conv_gemm_k<1,1, 64, 64, 512, 256,false,true , 64, 64,16,1><<<dim3( 64,4,1), 256, SM_1X1>>>(c3, l3, p4, p3);
    // RPN head path
    conv_gemm_k<3,1, 64, 64, 256, 256,false,false,128,128,32,9><<<dim3( 32,2,9), 256, SM_BIG>>>(p3, o3, nullptr, op);
    combine_k<false, 9><<<1024, 256>>>(op, p3o, 4096 * 256 / 4);
    conv_gemm_k<3,1, 64, 64, 256, 256,false,false,128,128,32,9><<<dim3( 32,2,9), 256, SM_BIG>>>(p3o, w_rpn, nullptr, op);
    combine_k<true, 9><<<1024, 256>>>(op, tb, 4096 * 256 / 4);
    obj_kernel<<<512, 256>>>(tb, w_obj, sc);
    nms_kernel<<<1, 1024>>>(sc, out);
}